// round 16
// baseline (speedup 1.0000x reference)
#include <cuda_runtime.h>

// NeuralTMT — GB300 sm_103a, round 16.
// K1 gather reverted to the round-13 layout (2 half-lane streams, occ 8 —
// best measured), PLUS 256 tail prefetch blocks that pull K2's IL/UI/IU rows
// into L2 during K1's drain waves. K2 unchanged.
// Inputs (metadata order): IL[4,V,64] f32, LI[4,V,64] f32, UI[4,U,64] f32,
// IU[V,64] f32, alpha[4] f32, uid[B] i32, baskets[4,B,50] i32,
// iid[4,B] i32, neg_iid[4,B] i32. Output f32[8*B].

#define TMT_V 100001
#define TMT_U 100000
#define TMT_K 64
#define TMT_B 16384
#define TMT_L 50
#define TMT_NEG_BIG (-4294967295.0f)   // -(2^32)+1
#define K1_NB 8                         // batch elements per K1 gather CTA
#define GATHER_BLOCKS (4 * (TMT_B / K1_NB))   // 8192
#define PF_BLOCKS 256

// Scratch: x[b][period][k]  (16384 * 4 * 64 f32 = 16.8 MB)
__device__ float g_x[(long long)TMT_B * 4 * TMT_K];
// Prefetch sink (never read; keeps prefetch loads live). 64K floats.
__device__ float g_pf_sink[PF_BLOCKS * 256];

__device__ __forceinline__ float dot4(float4 a, float4 b) {
    return a.x * b.x + a.y * b.y + a.z * b.z + a.w * b.w;
}

// ---------------------------------------------------------------------------
// K1: blocks [0, 8192): x[b,p,:] = (1/L) * sum_l LI[p, baskets[p,b,l], :]
//     period-major: p = blockIdx.x >> 11.
//     blocks [8192, 8448): L2 prefetch of K2's gather rows (runs in K1 tail).
// ---------------------------------------------------------------------------
__global__ __launch_bounds__(256, 8)
void tmt_gather_kernel(const float* __restrict__ LI,
                       const int*   __restrict__ baskets,
                       const float* __restrict__ IL,
                       const float* __restrict__ UI,
                       const float* __restrict__ IU,
                       const int*   __restrict__ uid,
                       const int*   __restrict__ iid,
                       const int*   __restrict__ neg_iid)
{
    if (blockIdx.x >= GATHER_BLOCKS) {
        // ---- prefetch role: one (p,b) pair per thread -----------------
        const int tidg = (blockIdx.x - GATHER_BLOCKS) * 256 + threadIdx.x;
        const int p = tidg >> 14;                // 0..3
        const int b = tidg & (TMT_B - 1);

        const int ip = __ldg(iid + p * TMT_B + b);
        const int in = __ldg(neg_iid + p * TMT_B + b);
        const int u  = __ldg(uid + b);

        const float4* r0 = (const float4*)(IL + ((long long)p * TMT_V + ip) * TMT_K);
        const float4* r1 = (const float4*)(IL + ((long long)p * TMT_V + in) * TMT_K);
        const float4* r2 = (const float4*)(UI + ((long long)p * TMT_U + u) * TMT_K);
        const float4* r3 = (const float4*)(IU + (long long)ip * TMT_K);
        const float4* r4 = (const float4*)(IU + (long long)in * TMT_K);

        float acc = 0.0f;
        #pragma unroll
        for (int i = 0; i < 16; ++i) {
            acc += __ldg(r0 + i).x + __ldg(r1 + i).x + __ldg(r2 + i).x
                 + __ldg(r3 + i).x + __ldg(r4 + i).x;
        }
        g_pf_sink[tidg] = acc;                   // deterministic, never read
        return;
    }

    // ---- gather role (round-13 layout) -----------------------------------
    __shared__ int sidx[K1_NB * TMT_L];          // 400 ints

    const int p  = blockIdx.x >> 11;             // period (period-major)
    const int bx = blockIdx.x & 2047;
    const int b0 = bx * K1_NB;
    const int t  = threadIdx.x;

    const int* bb = baskets + ((long long)p * TMT_B + b0) * TMT_L;
    #pragma unroll
    for (int i = t; i < K1_NB * TMT_L; i += 256)
        sidx[i] = bb[i];
    __syncthreads();

    const int bl   = t >> 5;                     // 0..7 local batch element
    const int lane = t & 31;
    const int h    = lane >> 4;                  // half 0/1: 25 l's each
    const int q    = lane & 15;                  // float4 slot (k = 4q)

    const float4* LIs = (const float4*)(LI + (long long)p * TMT_V * TMT_K) + q;
    const int* idxp = sidx + bl * TMT_L + h * 25;

    float4 acc = make_float4(0.f, 0.f, 0.f, 0.f);
    #pragma unroll
    for (int l = 0; l < 25; ++l) {
        const int idx = idxp[l];                 // broadcast LDS
        const float4 v = __ldg(LIs + (long long)idx * (TMT_K / 4));
        acc.x += v.x; acc.y += v.y; acc.z += v.z; acc.w += v.w;
    }

    // Combine the two halves (lane ^ 16 has the same (bl, q)).
    acc.x += __shfl_xor_sync(0xffffffffu, acc.x, 16);
    acc.y += __shfl_xor_sync(0xffffffffu, acc.y, 16);
    acc.z += __shfl_xor_sync(0xffffffffu, acc.z, 16);
    acc.w += __shfl_xor_sync(0xffffffffu, acc.w, 16);

    if (h == 0) {
        const float inv = 1.0f / (float)TMT_L;
        acc.x *= inv; acc.y *= inv; acc.z *= inv; acc.w *= inv;
        float4* xp =
            (float4*)(g_x + (((long long)(b0 + bl)) * 4 + p) * TMT_K) + q;
        *xp = acc;
    }
}

// ---------------------------------------------------------------------------
// K2: 8-lane sub-warp per (b_local, period, pos/neg) task.
// 256 threads = 8 warps = 32 groups = 32 tasks = 4 batch elements per CTA.
// ---------------------------------------------------------------------------
__global__ __launch_bounds__(256, 8)
void tmt_score_kernel(const float* __restrict__ IL,
                      const float* __restrict__ UI,
                      const float* __restrict__ IU,
                      const float* __restrict__ alpha,
                      const int*   __restrict__ uid,
                      const int*   __restrict__ iid,
                      const int*   __restrict__ neg_iid,
                      float*       __restrict__ out)
{
    __shared__ float xs[4][4][TMT_K];            // [b_local][period][k] = 4 KB

    const int t  = threadIdx.x;
    const int b0 = blockIdx.x * 4;

    // Stage x for this CTA's 4 batch elements (contiguous 4 KB in g_x).
    {
        const float4* src = (const float4*)(g_x + (long long)b0 * 4 * TMT_K);
        float4* dst = (float4*)&xs[0][0][0];
        #pragma unroll
        for (int i = t; i < 4 * 4 * TMT_K / 4; i += 256)
            dst[i] = src[i];
    }
    __syncthreads();

    const int w    = t >> 5;                     // warp 0..7
    const int lane = t & 31;
    const int g    = lane >> 3;                  // group 0..3 within warp
    const int kl   = lane & 7;                   // lane within group

    const int task = w * 4 + g;                  // 0..31
    const int bl   = task >> 3;                  // b_local
    const int p    = (task >> 1) & 3;            // period
    const int neg  = task & 1;
    const int gb   = b0 + bl;

    const int item = __ldg((neg ? neg_iid : iid) + p * TMT_B + gb);

    // Target row: two float4 per lane, coalesced 128 B per group request.
    const float4* tgt4 =
        (const float4*)(IL + ((long long)p * TMT_V + item) * TMT_K);
    const float4 ta = __ldg(tgt4 + kl);
    const float4 tc = __ldg(tgt4 + 8 + kl);

    // Partial dots over this lane's 8 k-elements.
    const float4* xs0 = (const float4*)xs[bl][0];
    const float4* xs1 = (const float4*)xs[bl][1];
    const float4* xs2 = (const float4*)xs[bl][2];
    const float4* xs3 = (const float4*)xs[bl][3];
    float d0 = dot4(xs0[kl], ta) + dot4(xs0[8 + kl], tc);
    float d1 = dot4(xs1[kl], ta) + dot4(xs1[8 + kl], tc);
    float d2 = dot4(xs2[kl], ta) + dot4(xs2[8 + kl], tc);
    float d3 = dot4(xs3[kl], ta) + dot4(xs3[8 + kl], tc);

    const float4* u4 =
        (const float4*)(UI + ((long long)p * TMT_U + __ldg(uid + gb)) * TMT_K);
    const float4* iu4 = (const float4*)(IU + (long long)item * TMT_K);
    float dm = dot4(__ldg(u4 + kl), __ldg(iu4 + kl))
             + dot4(__ldg(u4 + 8 + kl), __ldg(iu4 + 8 + kl));

    // 3-stage butterfly within each 8-lane group.
    #pragma unroll
    for (int off = 4; off > 0; off >>= 1) {
        d0 += __shfl_xor_sync(0xffffffffu, d0, off);
        d1 += __shfl_xor_sync(0xffffffffu, d1, off);
        d2 += __shfl_xor_sync(0xffffffffu, d2, off);
        d3 += __shfl_xor_sync(0xffffffffu, d3, off);
        dm += __shfl_xor_sync(0xffffffffu, dm, off);
    }

    if (kl == 0) {
        float d[4] = {d0, d1, d2, d3};
        float wv[4];
        float mx = -3.402823466e38f;
        #pragma unroll
        for (int i = 0; i < 4; ++i) {
            float v = d[i] * 0.125f;             // / sqrt(64)
            if (v == 0.0f) v = TMT_NEG_BIG;      // mask exact zeros
            wv[i] = v;
            mx = fmaxf(mx, v);
        }
        float sum = 0.0f;
        #pragma unroll
        for (int i = 0; i < 4; ++i) { wv[i] = expf(wv[i] - mx); sum += wv[i]; }
        float attn = 0.0f;
        #pragma unroll
        for (int i = 0; i < 4; ++i) attn += wv[i] * d[i];
        attn /= sum;

        const float a  = __ldg(alpha + p);
        const float sg = 1.0f / (1.0f + expf(-a));
        out[(2 * p + neg) * TMT_B + gb] = sg * attn + (1.0f - sg) * dm;
    }
}

extern "C" void kernel_launch(void* const* d_in, const int* in_sizes, int n_in,
                              void* d_out, int out_size)
{
    const float* IL      = (const float*)d_in[0];
    const float* LI      = (const float*)d_in[1];
    const float* UI      = (const float*)d_in[2];
    const float* IU      = (const float*)d_in[3];
    const float* alpha   = (const float*)d_in[4];
    const int*   uid     = (const int*)  d_in[5];
    const int*   baskets = (const int*)  d_in[6];
    const int*   iid     = (const int*)  d_in[7];
    const int*   neg_iid = (const int*)  d_in[8];
    float*       out     = (float*)d_out;

    tmt_gather_kernel<<<GATHER_BLOCKS + PF_BLOCKS, 256>>>(
        LI, baskets, IL, UI, IU, uid, iid, neg_iid);
    tmt_score_kernel<<<TMT_B / 4, 256>>>(IL, UI, IU, alpha, uid,
                                         iid, neg_iid, out);
}

// round 17
// speedup vs baseline: 1.8805x; 1.8805x over previous
#include <cuda_runtime.h>

// NeuralTMT — GB300 sm_103a, round 17: revert to round-13 structure (best:
// 64.0 us) + two register-neutral tweaks: K2 stages UI rows in smem (dedup
// pos/neg pairs, shorter load chain); K1 writes scratch with __stcs.
// Inputs (metadata order): IL[4,V,64] f32, LI[4,V,64] f32, UI[4,U,64] f32,
// IU[V,64] f32, alpha[4] f32, uid[B] i32, baskets[4,B,50] i32,
// iid[4,B] i32, neg_iid[4,B] i32. Output f32[8*B].

#define TMT_V 100001
#define TMT_U 100000
#define TMT_K 64
#define TMT_B 16384
#define TMT_L 50
#define TMT_NEG_BIG (-4294967295.0f)   // -(2^32)+1
#define K1_NB 8                         // batch elements per K1 CTA

// Scratch: x[b][period][k]  (16384 * 4 * 64 f32 = 16.8 MB)
__device__ float g_x[(long long)TMT_B * 4 * TMT_K];

__device__ __forceinline__ float dot4(float4 a, float4 b) {
    return a.x * b.x + a.y * b.y + a.z * b.z + a.w * b.w;
}

// ---------------------------------------------------------------------------
// K1: x[b,p,:] = (1/L) * sum_l LI[p, baskets[p,b,l], :]
// grid = (B/8, 4), blockIdx.y = period (period-major dispatch order).
// Warp covers one b: lane = h*16 + q; h in {0,1} sums 25 basket rows each
// over float4 slot q; partials combined with shfl_xor(16).
// ---------------------------------------------------------------------------
__global__ __launch_bounds__(256, 8)
void tmt_gather_kernel(const float* __restrict__ LI,
                       const int*   __restrict__ baskets)
{
    __shared__ int sidx[K1_NB * TMT_L];          // 400 ints

    const int p  = blockIdx.y;
    const int b0 = blockIdx.x * K1_NB;
    const int t  = threadIdx.x;

    // Strided stage — 400 ints, 256 threads.
    const int* bb = baskets + ((long long)p * TMT_B + b0) * TMT_L;
    #pragma unroll
    for (int i = t; i < K1_NB * TMT_L; i += 256)
        sidx[i] = bb[i];
    __syncthreads();

    const int bl   = t >> 5;                     // 0..7 local batch element
    const int lane = t & 31;
    const int h    = lane >> 4;                  // half 0/1: 25 l's each
    const int q    = lane & 15;                  // float4 slot (k = 4q)

    const float4* LIs = (const float4*)(LI + (long long)p * TMT_V * TMT_K) + q;
    const int* idxp = sidx + bl * TMT_L + h * 25;

    float4 acc = make_float4(0.f, 0.f, 0.f, 0.f);
    #pragma unroll
    for (int l = 0; l < 25; ++l) {
        const int idx = idxp[l];                 // broadcast LDS
        const float4 v = __ldg(LIs + (long long)idx * (TMT_K / 4));
        acc.x += v.x; acc.y += v.y; acc.z += v.z; acc.w += v.w;
    }

    // Combine the two halves (lane ^ 16 has the same (bl, q)).
    acc.x += __shfl_xor_sync(0xffffffffu, acc.x, 16);
    acc.y += __shfl_xor_sync(0xffffffffu, acc.y, 16);
    acc.z += __shfl_xor_sync(0xffffffffu, acc.z, 16);
    acc.w += __shfl_xor_sync(0xffffffffu, acc.w, 16);

    if (h == 0) {
        const float inv = 1.0f / (float)TMT_L;
        acc.x *= inv; acc.y *= inv; acc.z *= inv; acc.w *= inv;
        float4* xp =
            (float4*)(g_x + (((long long)(b0 + bl)) * 4 + p) * TMT_K) + q;
        __stcs(xp, acc);                         // evict-first: protect LI slice
    }
}

// ---------------------------------------------------------------------------
// K2: 8-lane sub-warp per (b_local, period, pos/neg) task.
// 256 threads = 8 warps = 32 groups = 32 tasks = 4 batch elements per CTA.
// UI rows staged in smem (pos/neg pairs share the same u row).
// ---------------------------------------------------------------------------
__global__ __launch_bounds__(256, 8)
void tmt_score_kernel(const float* __restrict__ IL,
                      const float* __restrict__ UI,
                      const float* __restrict__ IU,
                      const float* __restrict__ alpha,
                      const int*   __restrict__ uid,
                      const int*   __restrict__ iid,
                      const int*   __restrict__ neg_iid,
                      float*       __restrict__ out)
{
    __shared__ float xs[4][4][TMT_K];            // [b_local][period][k] = 4 KB
    __shared__ float us[4][4][TMT_K];            // [b_local][period][k] = 4 KB

    const int t  = threadIdx.x;
    const int b0 = blockIdx.x * 4;

    // Stage x for this CTA's 4 batch elements (contiguous 4 KB in g_x).
    {
        const float4* src = (const float4*)(g_x + (long long)b0 * 4 * TMT_K);
        float4* dst = (float4*)&xs[0][0][0];
        #pragma unroll
        for (int i = t; i < 4 * 4 * TMT_K / 4; i += 256)
            dst[i] = src[i];
    }
    // Stage the 16 UI rows: row r = bl*4 + p, 16 threads per row (float4).
    {
        const int r  = t >> 4;                   // 0..15
        const int q  = t & 15;                   // float4 slot
        const int bl = r >> 2;
        const int p  = r & 3;
        const int u  = __ldg(uid + b0 + bl);
        const float4* urow =
            (const float4*)(UI + ((long long)p * TMT_U + u) * TMT_K);
        ((float4*)us[bl][p])[q] = __ldg(urow + q);
    }
    __syncthreads();

    const int w    = t >> 5;                     // warp 0..7
    const int lane = t & 31;
    const int g    = lane >> 3;                  // group 0..3 within warp
    const int kl   = lane & 7;                   // lane within group

    const int task = w * 4 + g;                  // 0..31
    const int bl   = task >> 3;                  // b_local
    const int p    = (task >> 1) & 3;            // period
    const int neg  = task & 1;
    const int gb   = b0 + bl;

    const int item = __ldg((neg ? neg_iid : iid) + p * TMT_B + gb);

    // Target row: two float4 per lane, coalesced 128 B per group request.
    const float4* tgt4 =
        (const float4*)(IL + ((long long)p * TMT_V + item) * TMT_K);
    const float4 ta = __ldg(tgt4 + kl);
    const float4 tc = __ldg(tgt4 + 8 + kl);

    // Partial dots over this lane's 8 k-elements.
    const float4* xs0 = (const float4*)xs[bl][0];
    const float4* xs1 = (const float4*)xs[bl][1];
    const float4* xs2 = (const float4*)xs[bl][2];
    const float4* xs3 = (const float4*)xs[bl][3];
    float d0 = dot4(xs0[kl], ta) + dot4(xs0[8 + kl], tc);
    float d1 = dot4(xs1[kl], ta) + dot4(xs1[8 + kl], tc);
    float d2 = dot4(xs2[kl], ta) + dot4(xs2[8 + kl], tc);
    float d3 = dot4(xs3[kl], ta) + dot4(xs3[8 + kl], tc);

    const float4* up  = (const float4*)us[bl][p];
    const float4* iu4 = (const float4*)(IU + (long long)item * TMT_K);
    float dm = dot4(up[kl], __ldg(iu4 + kl))
             + dot4(up[8 + kl], __ldg(iu4 + 8 + kl));

    // 3-stage butterfly within each 8-lane group.
    #pragma unroll
    for (int off = 4; off > 0; off >>= 1) {
        d0 += __shfl_xor_sync(0xffffffffu, d0, off);
        d1 += __shfl_xor_sync(0xffffffffu, d1, off);
        d2 += __shfl_xor_sync(0xffffffffu, d2, off);
        d3 += __shfl_xor_sync(0xffffffffu, d3, off);
        dm += __shfl_xor_sync(0xffffffffu, dm, off);
    }

    if (kl == 0) {
        float d[4] = {d0, d1, d2, d3};
        float wv[4];
        float mx = -3.402823466e38f;
        #pragma unroll
        for (int i = 0; i < 4; ++i) {
            float v = d[i] * 0.125f;             // / sqrt(64)
            if (v == 0.0f) v = TMT_NEG_BIG;      // mask exact zeros
            wv[i] = v;
            mx = fmaxf(mx, v);
        }
        float sum = 0.0f;
        #pragma unroll
        for (int i = 0; i < 4; ++i) { wv[i] = expf(wv[i] - mx); sum += wv[i]; }
        float attn = 0.0f;
        #pragma unroll
        for (int i = 0; i < 4; ++i) attn += wv[i] * d[i];
        attn /= sum;

        const float a  = __ldg(alpha + p);
        const float sg = 1.0f / (1.0f + expf(-a));
        out[(2 * p + neg) * TMT_B + gb] = sg * attn + (1.0f - sg) * dm;
    }
}

extern "C" void kernel_launch(void* const* d_in, const int* in_sizes, int n_in,
                              void* d_out, int out_size)
{
    const float* IL      = (const float*)d_in[0];
    const float* LI      = (const float*)d_in[1];
    const float* UI      = (const float*)d_in[2];
    const float* IU      = (const float*)d_in[3];
    const float* alpha   = (const float*)d_in[4];
    const int*   uid     = (const int*)  d_in[5];
    const int*   baskets = (const int*)  d_in[6];
    const int*   iid     = (const int*)  d_in[7];
    const int*   neg_iid = (const int*)  d_in[8];
    float*       out     = (float*)d_out;

    dim3 g1(TMT_B / K1_NB, 4);
    tmt_gather_kernel<<<g1, 256>>>(LI, baskets);
    tmt_score_kernel<<<TMT_B / 4, 256>>>(IL, UI, IU, alpha, uid,
                                         iid, neg_iid, out);
}